// round 14
// baseline (speedup 1.0000x reference)
#include <cuda_runtime.h>

// Problem shape (fixed for this instance)
#define B_ 64
#define S_ 1024
#define L_ 16
#define T_ 32
#define AROW 20            // padded row stride (floats) for the 16x16 matrices
#define MSLOT (AROW * 16)  // 320 floats per matrix slot

#define LOG2E 1.4426950408889634f
#define LN2   0.6931471805599453f

// Scratch (static __device__ arrays — allocation-free per harness rules)
__device__ __align__(16) float g_P   [B_ * 8 * 256];   // chunk matrices (incl. folded tail chunk)
__device__             float g_nump[B_ * 8];           // per-(b,chunk) numerator partials
__device__             int   g_CP  [B_ * 8];           // chunk scale exponents

__device__ __forceinline__ float ex2f_(float x) {
    float r; asm("ex2.approx.f32 %0, %1;" : "=f"(r) : "f"(x)); return r;
}
__device__ __forceinline__ float lg2f_(float x) {
    float r; asm("lg2.approx.f32 %0, %1;" : "=f"(r) : "f"(x)); return r;
}
__device__ __forceinline__ int clampd_(int d) {
    return d < -120 ? -120 : (d > 120 ? 120 : d);
}
__device__ __forceinline__ int expo_(float x) {
    return (__float_as_int(x) >> 23) & 255;
}

// ---------------------------------------------------------------------------
// 16x16 matrix product D = Am * Bm, one column (hl) per 16-lane group.
// Row-major, row stride AROW. Result max-normalized to ~2^0.
// Dst may alias Bm (column-private per lane). Warp-uniform caller required.
// ---------------------------------------------------------------------------
__device__ __forceinline__ void matmul16(
    const float* Am, const float* Bm, float* Dst,
    int Ca, int Cb, int* Cdst, int hl)
{
    float bc[16];
#pragma unroll
    for (int k = 0; k < 16; k++) bc[k] = Bm[k * AROW + hl];

    float r[16];
#pragma unroll
    for (int i = 0; i < 16; i++) {
        const float4* ar = reinterpret_cast<const float4*>(Am + i * AROW);
        float4 a0 = ar[0], a1 = ar[1], a2 = ar[2], a3 = ar[3];
        float s0 = a0.x * bc[0];
        s0 = fmaf(a0.y, bc[1], s0); s0 = fmaf(a0.z, bc[2], s0); s0 = fmaf(a0.w, bc[3], s0);
        float s1 = a1.x * bc[4];
        s1 = fmaf(a1.y, bc[5], s1); s1 = fmaf(a1.z, bc[6], s1); s1 = fmaf(a1.w, bc[7], s1);
        float s2 = a2.x * bc[8];
        s2 = fmaf(a2.y, bc[9], s2); s2 = fmaf(a2.z, bc[10], s2); s2 = fmaf(a2.w, bc[11], s2);
        float s3 = a3.x * bc[12];
        s3 = fmaf(a3.y, bc[13], s3); s3 = fmaf(a3.z, bc[14], s3); s3 = fmaf(a3.w, bc[15], s3);
        r[i] = (s0 + s1) + (s2 + s3);
    }

    int ex = 0;
#pragma unroll
    for (int i = 0; i < 16; i++) ex = max(ex, expo_(r[i]));
    ex = max(ex, __shfl_xor_sync(0xffffffffu, ex, 1, 16));
    ex = max(ex, __shfl_xor_sync(0xffffffffu, ex, 2, 16));
    ex = max(ex, __shfl_xor_sync(0xffffffffu, ex, 4, 16));
    ex = max(ex, __shfl_xor_sync(0xffffffffu, ex, 8, 16));
    int d = clampd_(ex - 127);
    float sc = __int_as_float((127 - d) << 23);
#pragma unroll
    for (int i = 0; i < 16; i++) Dst[i * AROW + hl] = r[i] * sc;
    if (hl == 0) *Cdst = Ca + Cb + d;
}

// Serial matvec: vf <- normalize(M * vf); row hl per lane, vf replicated on
// all 32 lanes (halves mirror via width-16 shfl). Warp-uniform caller.
__device__ __forceinline__ void matvec16(
    const float* __restrict__ M, int Cm, float* vf, int& Cv, int hl)
{
    const float4* rp = reinterpret_cast<const float4*>(M + hl * AROW);
    float4 c0 = rp[0], c1 = rp[1], c2 = rp[2], c3 = rp[3];
    float a0 = c0.x * vf[0];
    a0 = fmaf(c0.y, vf[1], a0); a0 = fmaf(c0.z, vf[2], a0); a0 = fmaf(c0.w, vf[3], a0);
    float a1 = c1.x * vf[4];
    a1 = fmaf(c1.y, vf[5], a1); a1 = fmaf(c1.z, vf[6], a1); a1 = fmaf(c1.w, vf[7], a1);
    float a2 = c2.x * vf[8];
    a2 = fmaf(c2.y, vf[9], a2); a2 = fmaf(c2.z, vf[10], a2); a2 = fmaf(c2.w, vf[11], a2);
    float a3 = c3.x * vf[12];
    a3 = fmaf(c3.y, vf[13], a3); a3 = fmaf(c3.z, vf[14], a3); a3 = fmaf(c3.w, vf[15], a3);
    float s = (a0 + a1) + (a2 + a3);
#pragma unroll
    for (int k = 0; k < 16; k++) vf[k] = __shfl_sync(0xffffffffu, s, k, 16);
    // balanced max-exponent tree
    int e0 = max(expo_(vf[0]),  expo_(vf[1])),  e1 = max(expo_(vf[2]),  expo_(vf[3]));
    int e2 = max(expo_(vf[4]),  expo_(vf[5])),  e3 = max(expo_(vf[6]),  expo_(vf[7]));
    int e4 = max(expo_(vf[8]),  expo_(vf[9])),  e5 = max(expo_(vf[10]), expo_(vf[11]));
    int e6 = max(expo_(vf[12]), expo_(vf[13])), e7 = max(expo_(vf[14]), expo_(vf[15]));
    int ex = max(max(max(e0, e1), max(e2, e3)), max(max(e4, e5), max(e6, e7)));
    int d = clampd_(ex - 127);
    Cv += d + Cm;
    float sc = __int_as_float((127 - d) << 23);
#pragma unroll
    for (int k = 0; k < 16; k++) vf[k] *= sc;
}

// ---------------------------------------------------------------------------
// Kernel FUSED: 512 blocks (64 batches x 8 chunks) x 512 threads.
// Streaming identical to R8. NEW: the tail block snapshots the partial
// segment's ring state at s == rem (block-uniform), stores a rem-step matrix
// + identity padding, and runs the same 8->1 fold as full blocks — so every
// active block exports exactly one chunk matrix and the scan needs no raw
// tail replay.
// ---------------------------------------------------------------------------
__global__ __launch_bounds__(512) void semicrf_fused(
    const float* __restrict__ tr,
    const int*   __restrict__ tags,
    const int*   __restrict__ lens,
    float*       __restrict__ out)
{
    __shared__ float sA[8 * MSLOT];
    __shared__ int   sC[8];
    __shared__ float sNum[16];

    const int b    = blockIdx.x >> 3;
    const int c    = blockIdx.x & 7;
    const int tid  = threadIdx.x;
    const int warp = tid >> 5;
    const int lane = tid & 31;
    const int half = lane >> 4;
    const int hl   = lane & 15;
    const int sub  = lane >> 3;

    if (blockIdx.x == 0 && tid == 0) out[0] = 0.0f;

    const int len  = lens[b];
    const int m    = len >> 4;
    const int rem  = len & 15;
    const int qc   = m >> 3;
    const int tseg = m & 7;

    const bool full  = (c < qc);
    const bool tailb = (c == qc);
    const int nt = full ? 128 : (tailb ? (tseg * 16 + (rem > 0 ? 16 : 0)) : 0);

    // ---- numerator gather: lane t (<8) handles tile warp*8+t ----
    {
        float ncv = 0.0f;
        if (lane < 8) {
            int e = c * 128 + warp * 8 + lane;
            if (e < len) {
                int tag = tags[b * S_ + e];
                ncv = tr[((size_t)(b * S_ + e)) * 512 + tag];
            }
        }
#pragma unroll
        for (int o = 4; o > 0; o >>= 1) ncv += __shfl_xor_sync(0xffffffffu, ncv, o);
        if (lane == 0) sNum[warp] = ncv;
    }

    if (nt == 0) {   // block-uniform early exit (chunk beyond len)
        __syncthreads();
        if (warp == 0 && tailb) {   // record the (zero) numerator partial
            float np = (lane < 16) ? sNum[lane] : 0.0f;
#pragma unroll
            for (int o = 8; o > 0; o >>= 1) np += __shfl_xor_sync(0xffffffffu, np, o);
            if (lane == 0) g_nump[b * 8 + c] = np;
        }
        return;
    }

    // ---- zero-fill unstaged segment slots in tail blocks ----
    if (!full) {
        for (int i = tid; i < 8 * MSLOT; i += 512) sA[i] = 0.0f;
        __syncthreads();
    }

    // ---- phase 1: w row-sums for this warp's needed tiles (pipelined) ----
    {
        const float4* tb = reinterpret_cast<const float4*>(tr)
                         + ((size_t)(b * S_ + c * 128 + warp * 8)) * 128;
        const int base = warp * 8;
        float4 cur[4], nxt[4];
        if (base < nt) {
#pragma unroll
            for (int i = 0; i < 4; i++) cur[i] = __ldcs(&tb[i * 32 + lane]);
        }
#pragma unroll
        for (int t8 = 0; t8 < 8; t8++) {
            const int tile = base + t8;          // warp-uniform
            if (tile >= nt) break;
            if (tile + 1 < nt) {
#pragma unroll
                for (int i = 0; i < 4; i++)
                    nxt[i] = __ldcs(&tb[(t8 + 1) * 128 + i * 32 + lane]);
            }
            float rs[4];
#pragma unroll
            for (int i = 0; i < 4; i++) {
                float4 v = cur[i];
                float s = ex2f_(v.x * LOG2E) + ex2f_(v.y * LOG2E)
                        + ex2f_(v.z * LOG2E) + ex2f_(v.w * LOG2E);
                s += __shfl_xor_sync(0xffffffffu, s, 1);
                s += __shfl_xor_sync(0xffffffffu, s, 2);
                s += __shfl_xor_sync(0xffffffffu, s, 4);
                rs[i] = s;
            }
            if ((lane & 7) == 0) {
                float* wb = sA + (tile >> 4) * MSLOT + (tile & 15) * 16;
#pragma unroll
                for (int i = 0; i < 4; i++) wb[i * 4 + sub] = rs[i];
            }
#pragma unroll
            for (int i = 0; i < 4; i++) cur[i] = nxt[i];
        }
    }
    __syncthreads();

    // ---- numerator partial store (warp 5) ----
    if (warp == 5) {
        float np = (lane < 16) ? sNum[lane] : 0.0f;
#pragma unroll
        for (int o = 8; o > 0; o >>= 1) np += __shfl_xor_sync(0xffffffffu, np, o);
        if (lane == 0) g_nump[b * 8 + c] = np;
    }

    // ---- phase 2: build level-0 matrices (warps 0-3, WARP-UNIFORM) ----
    // Every builder also snapshots its ring state at s == rem (block-uniform
    // condition). The tail block's partial-segment slot stores the snapshot.
    const int segl = warp * 2 + half;
    float zzb[16], zzp[16];
    int   Cb2 = 0, Cp = 0;
    if (warp < 4) {
        const float4* wv = reinterpret_cast<const float4*>(sA + segl * MSLOT);

#pragma unroll
        for (int k = 0; k < 16; k++) zzb[k] = (k == ((16 - hl) & 15)) ? 1.0f : 0.0f;
#pragma unroll
        for (int k = 0; k < 16; k++) zzp[k] = zzb[k];

#pragma unroll
        for (int s = 0; s < 16; s++) {
            if (s == rem) {               // snapshot state after s steps
#pragma unroll
                for (int k = 0; k < 16; k++) zzp[k] = zzb[k];
                Cp = Cb2;
            }
            float4 rr0 = wv[s * 4 + 0], rr1 = wv[s * 4 + 1];
            float4 rr2 = wv[s * 4 + 2], rr3 = wv[s * 4 + 3];

            float p3 = zzb[(s - 15 + 32) & 15] * rr3.w;
            p3 = fmaf(zzb[(s - 14 + 32) & 15], rr3.z, p3);
            p3 = fmaf(zzb[(s - 13 + 32) & 15], rr3.y, p3);
            p3 = fmaf(zzb[(s - 12 + 32) & 15], rr3.x, p3);
            float p2 = zzb[(s - 11 + 32) & 15] * rr2.w;
            p2 = fmaf(zzb[(s - 10 + 32) & 15], rr2.z, p2);
            p2 = fmaf(zzb[(s -  9 + 32) & 15], rr2.y, p2);
            p2 = fmaf(zzb[(s -  8 + 32) & 15], rr2.x, p2);
            float p1 = zzb[(s -  7 + 32) & 15] * rr1.w;
            p1 = fmaf(zzb[(s -  6 + 32) & 15], rr1.z, p1);
            p1 = fmaf(zzb[(s -  5 + 32) & 15], rr1.y, p1);
            p1 = fmaf(zzb[(s -  4 + 32) & 15], rr1.x, p1);
            float p0 = zzb[(s -  3 + 32) & 15] * rr0.w;
            p0 = fmaf(zzb[(s -  2 + 32) & 15], rr0.z, p0);
            p0 = fmaf(zzb[(s -  1 + 32) & 15], rr0.y, p0);

            float zn = ((p3 + p2) + p1) + p0;
            zn = fmaf(zzb[s & 15], rr0.x, zn);
            zzb[(s + 1) & 15] = zn;

            if ((s & 3) == 3 && s != 15) {
                int ex = expo_(zn);
                ex = max(ex, __shfl_xor_sync(0xffffffffu, ex, 1, 16));
                ex = max(ex, __shfl_xor_sync(0xffffffffu, ex, 2, 16));
                ex = max(ex, __shfl_xor_sync(0xffffffffu, ex, 4, 16));
                ex = max(ex, __shfl_xor_sync(0xffffffffu, ex, 8, 16));
                int d = clampd_(ex - 127);
                Cb2 += d;
                float sc = __int_as_float((127 - d) << 23);
#pragma unroll
                for (int k2 = 0; k2 < 16; k2++) zzb[k2] *= sc;
            }
        }
        {   // final renorm of the full 16-step matrix
            int ex = 0;
#pragma unroll
            for (int k = 0; k < 16; k++) ex = max(ex, expo_(zzb[k]));
            ex = max(ex, __shfl_xor_sync(0xffffffffu, ex, 1, 16));
            ex = max(ex, __shfl_xor_sync(0xffffffffu, ex, 2, 16));
            ex = max(ex, __shfl_xor_sync(0xffffffffu, ex, 4, 16));
            ex = max(ex, __shfl_xor_sync(0xffffffffu, ex, 8, 16));
            int d = clampd_(ex - 127);
            Cb2 += d;
            float sc = __int_as_float((127 - d) << 23);
#pragma unroll
            for (int k = 0; k < 16; k++) zzb[k] *= sc;
        }
        {   // final renorm of the snapshot matrix (warp-uniform shuffles)
            int ex = 0;
#pragma unroll
            for (int k = 0; k < 16; k++) ex = max(ex, expo_(zzp[k]));
            ex = max(ex, __shfl_xor_sync(0xffffffffu, ex, 1, 16));
            ex = max(ex, __shfl_xor_sync(0xffffffffu, ex, 2, 16));
            ex = max(ex, __shfl_xor_sync(0xffffffffu, ex, 4, 16));
            ex = max(ex, __shfl_xor_sync(0xffffffffu, ex, 8, 16));
            int d = clampd_(ex - 127);
            Cp += d;
            float sc = __int_as_float((127 - d) << 23);
#pragma unroll
            for (int k = 0; k < 16; k++) zzp[k] *= sc;
        }
    }
    __syncthreads();   // all reads of staged w complete

    // store matrices (no shuffles below — per-half divergence is safe)
    if (warp < 4) {
        float* slot = sA + segl * MSLOT;
        if (full || segl < tseg) {                 // full 16-step matrix
#pragma unroll
            for (int i = 0; i < 16; i++) slot[i * AROW + hl] = zzb[(16 - i) & 15];
            if (hl == 0) sC[segl] = Cb2;
        } else if (segl == tseg && rem > 0) {      // rem-step partial matrix
#pragma unroll
            for (int i = 0; i < 16; i++) slot[i * AROW + hl] = zzp[(rem - i + 32) & 15];
            if (hl == 0) sC[segl] = Cp;
        } else {                                   // identity padding
#pragma unroll
            for (int i = 0; i < 16; i++) slot[i * AROW + hl] = (i == hl) ? 1.0f : 0.0f;
            if (hl == 0) sC[segl] = 0;
        }
    }
    __syncthreads();

    // ---- phase 3: fold 8 -> 4 -> 2 -> 1, in place (ALL active blocks) ----
    if (warp < 2) {
        int u = warp * 2 + half;
        matmul16(sA + (2 * u + 1) * MSLOT, sA + (2 * u) * MSLOT,
                 sA + (2 * u) * MSLOT, sC[2 * u + 1], sC[2 * u], &sC[2 * u], hl);
    }
    __syncthreads();
    if (warp == 0) {
        int u = half;
        matmul16(sA + (4 * u + 2) * MSLOT, sA + (4 * u) * MSLOT,
                 sA + (4 * u) * MSLOT, sC[4 * u + 2], sC[4 * u], &sC[4 * u], hl);
    }
    __syncthreads();
    if (warp == 0) {
        matmul16(sA + 4 * MSLOT, sA, sA, sC[4], sC[0], &sC[0], hl);
    }
    __syncthreads();

    if (tid < 256) {
        float* gp = g_P + ((size_t)b * 8 + c) * 256;
        gp[tid] = sA[(tid >> 4) * AROW + (tid & 15)];
        if (tid == 0) g_CP[b * 8 + c] = sC[0];
    }
}

// ---------------------------------------------------------------------------
// Kernel SCAN: 64 blocks x 256 threads. Stage <=8 chunk matrices; warp 0
// runs <=8 matvecs. No raw tail replay — the tail chunk matrix covers it.
// ---------------------------------------------------------------------------
__global__ __launch_bounds__(256) void semicrf_scan(
    const int* __restrict__ lens,
    float*     __restrict__ out)
{
    __shared__ float sM[8 * MSLOT];
    __shared__ int   sCm[8];

    const int b    = blockIdx.x;
    const int tid  = threadIdx.x;
    const int warp = tid >> 5;
    const int lane = tid & 31;
    const int hl   = lane & 15;

    const int len = lens[b];
    const int qc  = len >> 7;
    const int n_m = qc + (((len & 127) != 0) ? 1 : 0);   // <= 8
    const int tot = n_m * 256;

    // stage matrices: 8 independent predicated loads per thread, then store
    {
        float v[8];
#pragma unroll
        for (int r = 0; r < 8; r++) {
            int idx = tid + r * 256;
            v[r] = (idx < tot) ? g_P[(size_t)b * 2048 + idx] : 0.0f;
        }
#pragma unroll
        for (int r = 0; r < 8; r++) {
            int idx = tid + r * 256;
            if (idx < tot) {
                int j = idx >> 8, pos = idx & 255;
                sM[j * MSLOT + (pos >> 4) * AROW + (pos & 15)] = v[r];
            }
        }
    }
    if (tid < n_m) sCm[tid] = g_CP[b * 8 + tid];
    __syncthreads();

    if (warp == 0) {
        // numerator = sum of partials for chunks 0..min(qc,7)
        float nt = (lane < 8 && lane <= qc) ? g_nump[b * 8 + lane] : 0.0f;
#pragma unroll
        for (int o = 4; o > 0; o >>= 1) nt += __shfl_xor_sync(0xffffffffu, nt, o);
        nt = __shfl_sync(0xffffffffu, nt, 0);

        float vf[16];
#pragma unroll
        for (int k = 0; k < 16; k++) vf[k] = (k == 0) ? 1.0f : 0.0f;
        int Cv = 0;

        for (int j = 0; j < n_m; j++)
            matvec16(sM + j * MSLOT, sCm[j], vf, Cv, hl);

        float den = ((float)Cv + lg2f_(vf[0])) * LN2;

        if (lane == 0) atomicAdd(out, den - nt);
    }
}

// ---------------------------------------------------------------------------
extern "C" void kernel_launch(void* const* d_in, const int* in_sizes, int n_in,
                              void* d_out, int out_size)
{
    const float* tr   = (const float*)d_in[0];   // [B,S,L,T] f32
    const int*   tags = (const int*)  d_in[1];   // [B,S] i32
    const int*   lens = (const int*)  d_in[2];   // [B] i32
    float*       out  = (float*)d_out;           // scalar f32

    semicrf_fused<<<512, 512>>>(tr, tags, lens, out);   // stream + per-chunk fold
    semicrf_scan<<<64, 256>>>(lens, out);               // <=8 matvecs per batch
}

// round 16
// speedup vs baseline: 1.0252x; 1.0252x over previous
#include <cuda_runtime.h>

// Problem shape (fixed for this instance)
#define B_ 64
#define S_ 1024
#define L_ 16
#define T_ 32
#define AROW 20            // padded row stride (floats) for the 16x16 matrices
#define MSLOT (AROW * 16)  // 320 floats per matrix slot

#define LOG2E 1.4426950408889634f
#define LN2   0.6931471805599453f

// Scratch (static __device__ arrays — allocation-free per harness rules)
__device__ __align__(16) float g_P   [B_ * 8 * 256];   // chunk matrices (incl. folded tail chunk)
__device__             float g_nump[B_ * 8];           // per-(b,chunk) numerator partials
__device__             int   g_CP  [B_ * 8];           // chunk scale exponents

__device__ __forceinline__ float ex2f_(float x) {
    float r; asm("ex2.approx.f32 %0, %1;" : "=f"(r) : "f"(x)); return r;
}
__device__ __forceinline__ float lg2f_(float x) {
    float r; asm("lg2.approx.f32 %0, %1;" : "=f"(r) : "f"(x)); return r;
}
__device__ __forceinline__ int clampd_(int d) {
    return d < -120 ? -120 : (d > 120 ? 120 : d);
}
__device__ __forceinline__ int expo_(float x) {
    return (__float_as_int(x) >> 23) & 255;
}

// ---------------------------------------------------------------------------
// 16x16 matrix product D = Am * Bm, one column (hl) per 16-lane group.
// Row-major, row stride AROW. Result max-normalized to ~2^0.
// Dst may alias Bm (column-private per lane). Warp-uniform caller required.
// ---------------------------------------------------------------------------
__device__ __forceinline__ void matmul16(
    const float* Am, const float* Bm, float* Dst,
    int Ca, int Cb, int* Cdst, int hl)
{
    float bc[16];
#pragma unroll
    for (int k = 0; k < 16; k++) bc[k] = Bm[k * AROW + hl];

    float r[16];
#pragma unroll
    for (int i = 0; i < 16; i++) {
        const float4* ar = reinterpret_cast<const float4*>(Am + i * AROW);
        float4 a0 = ar[0], a1 = ar[1], a2 = ar[2], a3 = ar[3];
        float s0 = a0.x * bc[0];
        s0 = fmaf(a0.y, bc[1], s0); s0 = fmaf(a0.z, bc[2], s0); s0 = fmaf(a0.w, bc[3], s0);
        float s1 = a1.x * bc[4];
        s1 = fmaf(a1.y, bc[5], s1); s1 = fmaf(a1.z, bc[6], s1); s1 = fmaf(a1.w, bc[7], s1);
        float s2 = a2.x * bc[8];
        s2 = fmaf(a2.y, bc[9], s2); s2 = fmaf(a2.z, bc[10], s2); s2 = fmaf(a2.w, bc[11], s2);
        float s3 = a3.x * bc[12];
        s3 = fmaf(a3.y, bc[13], s3); s3 = fmaf(a3.z, bc[14], s3); s3 = fmaf(a3.w, bc[15], s3);
        r[i] = (s0 + s1) + (s2 + s3);
    }

    int ex = 0;
#pragma unroll
    for (int i = 0; i < 16; i++) ex = max(ex, expo_(r[i]));
    ex = max(ex, __shfl_xor_sync(0xffffffffu, ex, 1, 16));
    ex = max(ex, __shfl_xor_sync(0xffffffffu, ex, 2, 16));
    ex = max(ex, __shfl_xor_sync(0xffffffffu, ex, 4, 16));
    ex = max(ex, __shfl_xor_sync(0xffffffffu, ex, 8, 16));
    int d = clampd_(ex - 127);
    float sc = __int_as_float((127 - d) << 23);
#pragma unroll
    for (int i = 0; i < 16; i++) Dst[i * AROW + hl] = r[i] * sc;
    if (hl == 0) *Cdst = Ca + Cb + d;
}

// Serial matvec: vf <- normalize(M * vf); row hl per lane, vf replicated on
// all 32 lanes (halves mirror via width-16 shfl). Warp-uniform caller.
__device__ __forceinline__ void matvec16(
    const float* __restrict__ M, int Cm, float* vf, int& Cv, int hl)
{
    const float4* rp = reinterpret_cast<const float4*>(M + hl * AROW);
    float4 c0 = rp[0], c1 = rp[1], c2 = rp[2], c3 = rp[3];
    float a0 = c0.x * vf[0];
    a0 = fmaf(c0.y, vf[1], a0); a0 = fmaf(c0.z, vf[2], a0); a0 = fmaf(c0.w, vf[3], a0);
    float a1 = c1.x * vf[4];
    a1 = fmaf(c1.y, vf[5], a1); a1 = fmaf(c1.z, vf[6], a1); a1 = fmaf(c1.w, vf[7], a1);
    float a2 = c2.x * vf[8];
    a2 = fmaf(c2.y, vf[9], a2); a2 = fmaf(c2.z, vf[10], a2); a2 = fmaf(c2.w, vf[11], a2);
    float a3 = c3.x * vf[12];
    a3 = fmaf(c3.y, vf[13], a3); a3 = fmaf(c3.z, vf[14], a3); a3 = fmaf(c3.w, vf[15], a3);
    float s = (a0 + a1) + (a2 + a3);
#pragma unroll
    for (int k = 0; k < 16; k++) vf[k] = __shfl_sync(0xffffffffu, s, k, 16);
    int e0 = max(expo_(vf[0]),  expo_(vf[1])),  e1 = max(expo_(vf[2]),  expo_(vf[3]));
    int e2 = max(expo_(vf[4]),  expo_(vf[5])),  e3 = max(expo_(vf[6]),  expo_(vf[7]));
    int e4 = max(expo_(vf[8]),  expo_(vf[9])),  e5 = max(expo_(vf[10]), expo_(vf[11]));
    int e6 = max(expo_(vf[12]), expo_(vf[13])), e7 = max(expo_(vf[14]), expo_(vf[15]));
    int ex = max(max(max(e0, e1), max(e2, e3)), max(max(e4, e5), max(e6, e7)));
    int d = clampd_(ex - 127);
    Cv += d + Cm;
    float sc = __int_as_float((127 - d) << 23);
#pragma unroll
    for (int k = 0; k < 16; k++) vf[k] *= sc;
}

// ---------------------------------------------------------------------------
// Kernel FUSED: 512 blocks (64 batches x 8 chunks) x 512 threads.
// Streaming + build identical to R8. Tail handling via DATA, not registers:
// the partial segment's w rows s in [rem,16) are overwritten with e0
// (pure-shift steps), so the unchanged build loop emits a matrix whose row 0
// is the exact rem-step map. Tail blocks then fold 8->1 like full blocks.
// ---------------------------------------------------------------------------
__global__ __launch_bounds__(512) void semicrf_fused(
    const float* __restrict__ tr,
    const int*   __restrict__ tags,
    const int*   __restrict__ lens,
    float*       __restrict__ out)
{
    __shared__ float sA[8 * MSLOT];
    __shared__ int   sC[8];
    __shared__ float sNum[16];

    const int b    = blockIdx.x >> 3;
    const int c    = blockIdx.x & 7;
    const int tid  = threadIdx.x;
    const int warp = tid >> 5;
    const int lane = tid & 31;
    const int half = lane >> 4;
    const int hl   = lane & 15;
    const int sub  = lane >> 3;

    if (blockIdx.x == 0 && tid == 0) out[0] = 0.0f;

    const int len  = lens[b];
    const int m    = len >> 4;
    const int rem  = len & 15;
    const int qc   = m >> 3;
    const int tseg = m & 7;

    const bool full  = (c < qc);
    const bool tailb = (c == qc);
    const int nt = full ? 128 : (tailb ? (tseg * 16 + (rem > 0 ? 16 : 0)) : 0);

    // ---- numerator gather: lane t (<8) handles tile warp*8+t ----
    {
        float ncv = 0.0f;
        if (lane < 8) {
            int e = c * 128 + warp * 8 + lane;
            if (e < len) {
                int tag = tags[b * S_ + e];
                ncv = tr[((size_t)(b * S_ + e)) * 512 + tag];
            }
        }
#pragma unroll
        for (int o = 4; o > 0; o >>= 1) ncv += __shfl_xor_sync(0xffffffffu, ncv, o);
        if (lane == 0) sNum[warp] = ncv;
    }

    if (nt == 0) {   // block-uniform early exit (chunk beyond len)
        __syncthreads();
        if (warp == 0 && tailb) {   // record the (zero) numerator partial
            float np = (lane < 16) ? sNum[lane] : 0.0f;
#pragma unroll
            for (int o = 8; o > 0; o >>= 1) np += __shfl_xor_sync(0xffffffffu, np, o);
            if (lane == 0) g_nump[b * 8 + c] = np;
        }
        return;
    }

    // ---- zero-fill unstaged segment slots in tail blocks ----
    if (!full) {
        for (int i = tid; i < 8 * MSLOT; i += 512) sA[i] = 0.0f;
        __syncthreads();
    }

    // ---- phase 1: w row-sums for this warp's needed tiles (pipelined) ----
    {
        const float4* tb = reinterpret_cast<const float4*>(tr)
                         + ((size_t)(b * S_ + c * 128 + warp * 8)) * 128;
        const int base = warp * 8;
        float4 cur[4], nxt[4];
        if (base < nt) {
#pragma unroll
            for (int i = 0; i < 4; i++) cur[i] = __ldcs(&tb[i * 32 + lane]);
        }
#pragma unroll
        for (int t8 = 0; t8 < 8; t8++) {
            const int tile = base + t8;          // warp-uniform
            if (tile >= nt) break;
            if (tile + 1 < nt) {
#pragma unroll
                for (int i = 0; i < 4; i++)
                    nxt[i] = __ldcs(&tb[(t8 + 1) * 128 + i * 32 + lane]);
            }
            float rs[4];
#pragma unroll
            for (int i = 0; i < 4; i++) {
                float4 v = cur[i];
                float s = ex2f_(v.x * LOG2E) + ex2f_(v.y * LOG2E)
                        + ex2f_(v.z * LOG2E) + ex2f_(v.w * LOG2E);
                s += __shfl_xor_sync(0xffffffffu, s, 1);
                s += __shfl_xor_sync(0xffffffffu, s, 2);
                s += __shfl_xor_sync(0xffffffffu, s, 4);
                rs[i] = s;
            }
            if ((lane & 7) == 0) {
                float* wb = sA + (tile >> 4) * MSLOT + (tile & 15) * 16;
#pragma unroll
                for (int i = 0; i < 4; i++) wb[i * 4 + sub] = rs[i];
            }
#pragma unroll
            for (int i = 0; i < 4; i++) cur[i] = nxt[i];
        }
    }
    __syncthreads();

    // ---- tail block: convert partial-segment steps [rem,16) to pure shifts
    //      (w row <- e0). Block-uniform barrier below covers full blocks too.
    if (!full && rem > 0) {
        float* slot = sA + tseg * MSLOT;
        int cnt = (16 - rem) * 16;
        for (int idx = tid; idx < cnt; idx += 512) {
            int s = rem + (idx >> 4), j = idx & 15;
            slot[s * 16 + j] = (j == 0) ? 1.0f : 0.0f;
        }
    }
    __syncthreads();

    // ---- numerator partial store (warp 5) ----
    if (warp == 5) {
        float np = (lane < 16) ? sNum[lane] : 0.0f;
#pragma unroll
        for (int o = 8; o > 0; o >>= 1) np += __shfl_xor_sync(0xffffffffu, np, o);
        if (lane == 0) g_nump[b * 8 + c] = np;
    }

    // ---- phase 2: build level-0 matrices (warps 0-3, WARP-UNIFORM) ----
    const int segl = warp * 2 + half;
    float zzb[16];
    int   Cb2 = 0;
    if (warp < 4) {
        const float4* wv = reinterpret_cast<const float4*>(sA + segl * MSLOT);

#pragma unroll
        for (int k = 0; k < 16; k++) zzb[k] = (k == ((16 - hl) & 15)) ? 1.0f : 0.0f;

#pragma unroll
        for (int s = 0; s < 16; s++) {
            float4 rr0 = wv[s * 4 + 0], rr1 = wv[s * 4 + 1];
            float4 rr2 = wv[s * 4 + 2], rr3 = wv[s * 4 + 3];

            float p3 = zzb[(s - 15 + 32) & 15] * rr3.w;
            p3 = fmaf(zzb[(s - 14 + 32) & 15], rr3.z, p3);
            p3 = fmaf(zzb[(s - 13 + 32) & 15], rr3.y, p3);
            p3 = fmaf(zzb[(s - 12 + 32) & 15], rr3.x, p3);
            float p2 = zzb[(s - 11 + 32) & 15] * rr2.w;
            p2 = fmaf(zzb[(s - 10 + 32) & 15], rr2.z, p2);
            p2 = fmaf(zzb[(s -  9 + 32) & 15], rr2.y, p2);
            p2 = fmaf(zzb[(s -  8 + 32) & 15], rr2.x, p2);
            float p1 = zzb[(s -  7 + 32) & 15] * rr1.w;
            p1 = fmaf(zzb[(s -  6 + 32) & 15], rr1.z, p1);
            p1 = fmaf(zzb[(s -  5 + 32) & 15], rr1.y, p1);
            p1 = fmaf(zzb[(s -  4 + 32) & 15], rr1.x, p1);
            float p0 = zzb[(s -  3 + 32) & 15] * rr0.w;
            p0 = fmaf(zzb[(s -  2 + 32) & 15], rr0.z, p0);
            p0 = fmaf(zzb[(s -  1 + 32) & 15], rr0.y, p0);

            float zn = ((p3 + p2) + p1) + p0;
            zn = fmaf(zzb[s & 15], rr0.x, zn);
            zzb[(s + 1) & 15] = zn;

            if ((s & 3) == 3 && s != 15) {
                int ex = expo_(zn);
                ex = max(ex, __shfl_xor_sync(0xffffffffu, ex, 1, 16));
                ex = max(ex, __shfl_xor_sync(0xffffffffu, ex, 2, 16));
                ex = max(ex, __shfl_xor_sync(0xffffffffu, ex, 4, 16));
                ex = max(ex, __shfl_xor_sync(0xffffffffu, ex, 8, 16));
                int d = clampd_(ex - 127);
                Cb2 += d;
                float sc = __int_as_float((127 - d) << 23);
#pragma unroll
                for (int k2 = 0; k2 < 16; k2++) zzb[k2] *= sc;
            }
        }
        {   // final renorm: true matrix max -> ~2^0
            int ex = 0;
#pragma unroll
            for (int k = 0; k < 16; k++) ex = max(ex, expo_(zzb[k]));
            ex = max(ex, __shfl_xor_sync(0xffffffffu, ex, 1, 16));
            ex = max(ex, __shfl_xor_sync(0xffffffffu, ex, 2, 16));
            ex = max(ex, __shfl_xor_sync(0xffffffffu, ex, 4, 16));
            ex = max(ex, __shfl_xor_sync(0xffffffffu, ex, 8, 16));
            int d = clampd_(ex - 127);
            Cb2 += d;
            float sc = __int_as_float((127 - d) << 23);
#pragma unroll
            for (int k = 0; k < 16; k++) zzb[k] *= sc;
        }
    }
    __syncthreads();   // all reads of staged w complete

    // store matrices (no shuffles below — per-half divergence is safe)
    if (warp < 4) {
        float* slot = sA + segl * MSLOT;
        const bool valid = full || (segl < tseg) || (segl == tseg && rem > 0);
        if (valid) {       // genuine matrix (partial segment handled by shifts)
#pragma unroll
            for (int i = 0; i < 16; i++) slot[i * AROW + hl] = zzb[(16 - i) & 15];
            if (hl == 0) sC[segl] = Cb2;
        } else {           // identity padding
#pragma unroll
            for (int i = 0; i < 16; i++) slot[i * AROW + hl] = (i == hl) ? 1.0f : 0.0f;
            if (hl == 0) sC[segl] = 0;
        }
    }
    __syncthreads();

    // ---- phase 3: fold 8 -> 4 -> 2 -> 1, in place (ALL active blocks) ----
    if (warp < 2) {
        int u = warp * 2 + half;
        matmul16(sA + (2 * u + 1) * MSLOT, sA + (2 * u) * MSLOT,
                 sA + (2 * u) * MSLOT, sC[2 * u + 1], sC[2 * u], &sC[2 * u], hl);
    }
    __syncthreads();
    if (warp == 0) {
        int u = half;
        matmul16(sA + (4 * u + 2) * MSLOT, sA + (4 * u) * MSLOT,
                 sA + (4 * u) * MSLOT, sC[4 * u + 2], sC[4 * u], &sC[4 * u], hl);
    }
    __syncthreads();
    if (warp == 0) {
        matmul16(sA + 4 * MSLOT, sA, sA, sC[4], sC[0], &sC[0], hl);
    }
    __syncthreads();

    if (tid < 256) {
        float* gp = g_P + ((size_t)b * 8 + c) * 256;
        gp[tid] = sA[(tid >> 4) * AROW + (tid & 15)];
        if (tid == 0) g_CP[b * 8 + c] = sC[0];
    }
}

// ---------------------------------------------------------------------------
// Kernel SCAN: 64 blocks x 256 threads. Stage <=8 chunk matrices; warp 0
// runs <=8 matvecs. No raw tail replay — the tail chunk matrix covers it.
// ---------------------------------------------------------------------------
__global__ __launch_bounds__(256) void semicrf_scan(
    const int* __restrict__ lens,
    float*     __restrict__ out)
{
    __shared__ float sM[8 * MSLOT];
    __shared__ int   sCm[8];

    const int b    = blockIdx.x;
    const int tid  = threadIdx.x;
    const int warp = tid >> 5;
    const int lane = tid & 31;
    const int hl   = lane & 15;

    const int len = lens[b];
    const int qc  = len >> 7;
    const int n_m = qc + (((len & 127) != 0) ? 1 : 0);   // <= 8
    const int tot = n_m * 256;

    // stage matrices: 8 independent predicated loads per thread, then store
    {
        float v[8];
#pragma unroll
        for (int r = 0; r < 8; r++) {
            int idx = tid + r * 256;
            v[r] = (idx < tot) ? g_P[(size_t)b * 2048 + idx] : 0.0f;
        }
#pragma unroll
        for (int r = 0; r < 8; r++) {
            int idx = tid + r * 256;
            if (idx < tot) {
                int j = idx >> 8, pos = idx & 255;
                sM[j * MSLOT + (pos >> 4) * AROW + (pos & 15)] = v[r];
            }
        }
    }
    if (tid < n_m) sCm[tid] = g_CP[b * 8 + tid];
    __syncthreads();

    if (warp == 0) {
        // numerator = sum of partials for chunks 0..min(qc,7)
        float nt = (lane < 8 && lane <= qc) ? g_nump[b * 8 + lane] : 0.0f;
#pragma unroll
        for (int o = 4; o > 0; o >>= 1) nt += __shfl_xor_sync(0xffffffffu, nt, o);
        nt = __shfl_sync(0xffffffffu, nt, 0);

        float vf[16];
#pragma unroll
        for (int k = 0; k < 16; k++) vf[k] = (k == 0) ? 1.0f : 0.0f;
        int Cv = 0;

        for (int j = 0; j < n_m; j++)
            matvec16(sM + j * MSLOT, sCm[j], vf, Cv, hl);

        float den = ((float)Cv + lg2f_(vf[0])) * LN2;

        if (lane == 0) atomicAdd(out, den - nt);
    }
}

// ---------------------------------------------------------------------------
extern "C" void kernel_launch(void* const* d_in, const int* in_sizes, int n_in,
                              void* d_out, int out_size)
{
    const float* tr   = (const float*)d_in[0];   // [B,S,L,T] f32
    const int*   tags = (const int*)  d_in[1];   // [B,S] i32
    const int*   lens = (const int*)  d_in[2];   // [B] i32
    float*       out  = (float*)d_out;           // scalar f32

    semicrf_fused<<<512, 512>>>(tr, tags, lens, out);   // stream + per-chunk fold
    semicrf_scan<<<64, 256>>>(lens, out);               // <=8 matvecs per batch
}

// round 17
// speedup vs baseline: 1.1104x; 1.0831x over previous
#include <cuda_runtime.h>

// Problem shape (fixed for this instance)
#define B_ 64
#define S_ 1024
#define L_ 16
#define T_ 32
#define AROW 20            // padded row stride (floats) for the 16x16 matrices
#define MSLOT (AROW * 16)  // 320 floats per matrix slot

#define LOG2E 1.4426950408889634f
#define LN2   0.6931471805599453f

// Scratch (static __device__ arrays — allocation-free per harness rules)
__device__ __align__(16) float g_P   [B_ * 8 * 256];   // 128-step chunk matrices
__device__ __align__(16) float g_A0t [B_ * 8 * 256];   // level-0 matrices of the tail chunk
__device__ __align__(16) float g_tailw[B_ * 256];      // raw w rows for the <16-step tail
__device__             float g_nump[B_ * 8];           // per-(b,chunk) numerator partials
__device__             int   g_CP  [B_ * 8];           // chunk scale exponents
__device__             int   g_C0t [B_ * 8];           // tail-chunk level-0 exponents

__device__ __forceinline__ float ex2f_(float x) {
    float r; asm("ex2.approx.f32 %0, %1;" : "=f"(r) : "f"(x)); return r;
}
__device__ __forceinline__ float lg2f_(float x) {
    float r; asm("lg2.approx.f32 %0, %1;" : "=f"(r) : "f"(x)); return r;
}
__device__ __forceinline__ int clampd_(int d) {
    return d < -120 ? -120 : (d > 120 ? 120 : d);
}
__device__ __forceinline__ int expo_(float x) {
    return (__float_as_int(x) >> 23) & 255;
}

// ---------------------------------------------------------------------------
// 16x16 matrix product D = Am * Bm, one column (hl) per 16-lane group.
// Row-major, row stride AROW. Result max-normalized to ~2^0.
// Dst may alias Bm (column-private per lane). Warp-uniform caller required.
// ---------------------------------------------------------------------------
__device__ __forceinline__ void matmul16(
    const float* Am, const float* Bm, float* Dst,
    int Ca, int Cb, int* Cdst, int hl)
{
    float bc[16];
#pragma unroll
    for (int k = 0; k < 16; k++) bc[k] = Bm[k * AROW + hl];

    float r[16];
#pragma unroll
    for (int i = 0; i < 16; i++) {
        const float4* ar = reinterpret_cast<const float4*>(Am + i * AROW);
        float4 a0 = ar[0], a1 = ar[1], a2 = ar[2], a3 = ar[3];
        float s0 = a0.x * bc[0];
        s0 = fmaf(a0.y, bc[1], s0); s0 = fmaf(a0.z, bc[2], s0); s0 = fmaf(a0.w, bc[3], s0);
        float s1 = a1.x * bc[4];
        s1 = fmaf(a1.y, bc[5], s1); s1 = fmaf(a1.z, bc[6], s1); s1 = fmaf(a1.w, bc[7], s1);
        float s2 = a2.x * bc[8];
        s2 = fmaf(a2.y, bc[9], s2); s2 = fmaf(a2.z, bc[10], s2); s2 = fmaf(a2.w, bc[11], s2);
        float s3 = a3.x * bc[12];
        s3 = fmaf(a3.y, bc[13], s3); s3 = fmaf(a3.z, bc[14], s3); s3 = fmaf(a3.w, bc[15], s3);
        r[i] = (s0 + s1) + (s2 + s3);
    }

    int ex = 0;
#pragma unroll
    for (int i = 0; i < 16; i++) ex = max(ex, expo_(r[i]));
    ex = max(ex, __shfl_xor_sync(0xffffffffu, ex, 1, 16));
    ex = max(ex, __shfl_xor_sync(0xffffffffu, ex, 2, 16));
    ex = max(ex, __shfl_xor_sync(0xffffffffu, ex, 4, 16));
    ex = max(ex, __shfl_xor_sync(0xffffffffu, ex, 8, 16));
    int d = clampd_(ex - 127);
    float sc = __int_as_float((127 - d) << 23);
#pragma unroll
    for (int i = 0; i < 16; i++) Dst[i * AROW + hl] = r[i] * sc;
    if (hl == 0) *Cdst = Ca + Cb + d;
}

// Serial matvec: vf <- normalize(M * vf); row hl per lane, vf replicated on
// all 32 lanes (halves mirror via width-16 shfl). Warp-uniform caller.
__device__ __forceinline__ void matvec16(
    const float* __restrict__ M, int Cm, float* vf, int& Cv, int hl)
{
    const float4* rp = reinterpret_cast<const float4*>(M + hl * AROW);
    float4 c0 = rp[0], c1 = rp[1], c2 = rp[2], c3 = rp[3];
    float a0 = c0.x * vf[0];
    a0 = fmaf(c0.y, vf[1], a0); a0 = fmaf(c0.z, vf[2], a0); a0 = fmaf(c0.w, vf[3], a0);
    float a1 = c1.x * vf[4];
    a1 = fmaf(c1.y, vf[5], a1); a1 = fmaf(c1.z, vf[6], a1); a1 = fmaf(c1.w, vf[7], a1);
    float a2 = c2.x * vf[8];
    a2 = fmaf(c2.y, vf[9], a2); a2 = fmaf(c2.z, vf[10], a2); a2 = fmaf(c2.w, vf[11], a2);
    float a3 = c3.x * vf[12];
    a3 = fmaf(c3.y, vf[13], a3); a3 = fmaf(c3.z, vf[14], a3); a3 = fmaf(c3.w, vf[15], a3);
    float s = (a0 + a1) + (a2 + a3);
#pragma unroll
    for (int k = 0; k < 16; k++) vf[k] = __shfl_sync(0xffffffffu, s, k, 16);
    int e0 = max(expo_(vf[0]),  expo_(vf[1])),  e1 = max(expo_(vf[2]),  expo_(vf[3]));
    int e2 = max(expo_(vf[4]),  expo_(vf[5])),  e3 = max(expo_(vf[6]),  expo_(vf[7]));
    int e4 = max(expo_(vf[8]),  expo_(vf[9])),  e5 = max(expo_(vf[10]), expo_(vf[11]));
    int e6 = max(expo_(vf[12]), expo_(vf[13])), e7 = max(expo_(vf[14]), expo_(vf[15]));
    int ex = max(max(max(e0, e1), max(e2, e3)), max(max(e4, e5), max(e6, e7)));
    int d = clampd_(ex - 127);
    Cv += d + Cm;
    float sc = __int_as_float((127 - d) << 23);
#pragma unroll
    for (int k = 0; k < 16; k++) vf[k] *= sc;
}

// ---------------------------------------------------------------------------
// Kernel FUSED (verbatim R8/R11 — measured best ~15us): 512 blocks x 512.
// Tail blocks export level-0 matrices + raw tail w and exit before the fold.
// ---------------------------------------------------------------------------
__global__ __launch_bounds__(512) void semicrf_fused(
    const float* __restrict__ tr,
    const int*   __restrict__ tags,
    const int*   __restrict__ lens,
    float*       __restrict__ out)
{
    __shared__ float sA[8 * MSLOT];
    __shared__ int   sC[8];
    __shared__ float sNum[16];

    const int b    = blockIdx.x >> 3;
    const int c    = blockIdx.x & 7;
    const int tid  = threadIdx.x;
    const int warp = tid >> 5;
    const int lane = tid & 31;
    const int half = lane >> 4;
    const int hl   = lane & 15;
    const int sub  = lane >> 3;

    if (blockIdx.x == 0 && tid == 0) out[0] = 0.0f;

    const int len  = lens[b];
    const int m    = len >> 4;
    const int rem  = len & 15;
    const int qc   = m >> 3;
    const int tseg = m & 7;

    const bool full  = (c < qc);
    const bool tailb = (c == qc);
    const int nt = full ? 128 : (tailb ? (tseg * 16 + (rem > 0 ? 16 : 0)) : 0);

    // ---- numerator gather: lane t (<8) handles tile warp*8+t ----
    {
        float ncv = 0.0f;
        if (lane < 8) {
            int e = c * 128 + warp * 8 + lane;
            if (e < len) {
                int tag = tags[b * S_ + e];
                ncv = tr[((size_t)(b * S_ + e)) * 512 + tag];
            }
        }
#pragma unroll
        for (int o = 4; o > 0; o >>= 1) ncv += __shfl_xor_sync(0xffffffffu, ncv, o);
        if (lane == 0) sNum[warp] = ncv;
    }

    if (nt == 0) {   // block-uniform early exit
        __syncthreads();
        if (warp == 0 && tailb) {
            float np = (lane < 16) ? sNum[lane] : 0.0f;
#pragma unroll
            for (int o = 8; o > 0; o >>= 1) np += __shfl_xor_sync(0xffffffffu, np, o);
            if (lane == 0) g_nump[b * 8 + c] = np;
        }
        return;
    }

    // ---- zero-fill unstaged segment slots in tail blocks ----
    if (!full) {
        for (int i = tid; i < 8 * MSLOT; i += 512) sA[i] = 0.0f;
        __syncthreads();
    }

    // ---- phase 1: w row-sums for this warp's needed tiles (pipelined) ----
    {
        const float4* tb = reinterpret_cast<const float4*>(tr)
                         + ((size_t)(b * S_ + c * 128 + warp * 8)) * 128;
        const int base = warp * 8;
        float4 cur[4], nxt[4];
        if (base < nt) {
#pragma unroll
            for (int i = 0; i < 4; i++) cur[i] = __ldcs(&tb[i * 32 + lane]);
        }
#pragma unroll
        for (int t8 = 0; t8 < 8; t8++) {
            const int tile = base + t8;          // warp-uniform
            if (tile >= nt) break;
            if (tile + 1 < nt) {
#pragma unroll
                for (int i = 0; i < 4; i++)
                    nxt[i] = __ldcs(&tb[(t8 + 1) * 128 + i * 32 + lane]);
            }
            float rs[4];
#pragma unroll
            for (int i = 0; i < 4; i++) {
                float4 v = cur[i];
                float s = ex2f_(v.x * LOG2E) + ex2f_(v.y * LOG2E)
                        + ex2f_(v.z * LOG2E) + ex2f_(v.w * LOG2E);
                s += __shfl_xor_sync(0xffffffffu, s, 1);
                s += __shfl_xor_sync(0xffffffffu, s, 2);
                s += __shfl_xor_sync(0xffffffffu, s, 4);
                rs[i] = s;
            }
            if ((lane & 7) == 0) {
                float* wb = sA + (tile >> 4) * MSLOT + (tile & 15) * 16;
#pragma unroll
                for (int i = 0; i < 4; i++) wb[i * 4 + sub] = rs[i];
            }
#pragma unroll
            for (int i = 0; i < 4; i++) cur[i] = nxt[i];
        }
    }
    __syncthreads();

    // ---- numerator partial store (warp 5) ----
    if (warp == 5) {
        float np = (lane < 16) ? sNum[lane] : 0.0f;
#pragma unroll
        for (int o = 8; o > 0; o >>= 1) np += __shfl_xor_sync(0xffffffffu, np, o);
        if (lane == 0) g_nump[b * 8 + c] = np;
    }
    // ---- tail w export (warp 4) ----
    if (warp == 4 && tailb && rem > 0) {
        const float4* s4 = reinterpret_cast<const float4*>(sA + tseg * MSLOT);
        float4* d4 = reinterpret_cast<float4*>(g_tailw + b * 256);
        d4[lane]      = s4[lane];
        d4[lane + 32] = s4[lane + 32];
    }

    // ---- phase 2: build level-0 matrices (warps 0-3, WARP-UNIFORM) ----
    const int segl = warp * 2 + half;
    float zzb[16];
    int   Cb2 = 0;
    if (warp < 4) {
        const float4* wv = reinterpret_cast<const float4*>(sA + segl * MSLOT);

#pragma unroll
        for (int k = 0; k < 16; k++) zzb[k] = (k == ((16 - hl) & 15)) ? 1.0f : 0.0f;

#pragma unroll
        for (int s = 0; s < 16; s++) {
            float4 rr0 = wv[s * 4 + 0], rr1 = wv[s * 4 + 1];
            float4 rr2 = wv[s * 4 + 2], rr3 = wv[s * 4 + 3];

            float p3 = zzb[(s - 15 + 32) & 15] * rr3.w;
            p3 = fmaf(zzb[(s - 14 + 32) & 15], rr3.z, p3);
            p3 = fmaf(zzb[(s - 13 + 32) & 15], rr3.y, p3);
            p3 = fmaf(zzb[(s - 12 + 32) & 15], rr3.x, p3);
            float p2 = zzb[(s - 11 + 32) & 15] * rr2.w;
            p2 = fmaf(zzb[(s - 10 + 32) & 15], rr2.z, p2);
            p2 = fmaf(zzb[(s -  9 + 32) & 15], rr2.y, p2);
            p2 = fmaf(zzb[(s -  8 + 32) & 15], rr2.x, p2);
            float p1 = zzb[(s -  7 + 32) & 15] * rr1.w;
            p1 = fmaf(zzb[(s -  6 + 32) & 15], rr1.z, p1);
            p1 = fmaf(zzb[(s -  5 + 32) & 15], rr1.y, p1);
            p1 = fmaf(zzb[(s -  4 + 32) & 15], rr1.x, p1);
            float p0 = zzb[(s -  3 + 32) & 15] * rr0.w;
            p0 = fmaf(zzb[(s -  2 + 32) & 15], rr0.z, p0);
            p0 = fmaf(zzb[(s -  1 + 32) & 15], rr0.y, p0);

            float zn = ((p3 + p2) + p1) + p0;
            zn = fmaf(zzb[s & 15], rr0.x, zn);
            zzb[(s + 1) & 15] = zn;

            if ((s & 3) == 3 && s != 15) {
                int ex = expo_(zn);
                ex = max(ex, __shfl_xor_sync(0xffffffffu, ex, 1, 16));
                ex = max(ex, __shfl_xor_sync(0xffffffffu, ex, 2, 16));
                ex = max(ex, __shfl_xor_sync(0xffffffffu, ex, 4, 16));
                ex = max(ex, __shfl_xor_sync(0xffffffffu, ex, 8, 16));
                int d = clampd_(ex - 127);
                Cb2 += d;
                float sc = __int_as_float((127 - d) << 23);
#pragma unroll
                for (int k2 = 0; k2 < 16; k2++) zzb[k2] *= sc;
            }
        }
        {   // final renorm: true matrix max -> ~2^0
            int ex = 0;
#pragma unroll
            for (int k = 0; k < 16; k++) ex = max(ex, expo_(zzb[k]));
            ex = max(ex, __shfl_xor_sync(0xffffffffu, ex, 1, 16));
            ex = max(ex, __shfl_xor_sync(0xffffffffu, ex, 2, 16));
            ex = max(ex, __shfl_xor_sync(0xffffffffu, ex, 4, 16));
            ex = max(ex, __shfl_xor_sync(0xffffffffu, ex, 8, 16));
            int d = clampd_(ex - 127);
            Cb2 += d;
            float sc = __int_as_float((127 - d) << 23);
#pragma unroll
            for (int k = 0; k < 16; k++) zzb[k] *= sc;
        }
    }
    __syncthreads();   // all reads of staged w complete

    if (warp < 4) {
        if (full) {        // keep in SMEM for the fold
            float* slot = sA + segl * MSLOT;
#pragma unroll
            for (int i = 0; i < 16; i++) slot[i * AROW + hl] = zzb[(16 - i) & 15];
            if (hl == 0) sC[segl] = Cb2;
        } else if (segl < tseg) {   // tail chunk: export needed level-0s
            float* gd = g_A0t + ((size_t)b * 8 + segl) * 256;
#pragma unroll
            for (int i = 0; i < 16; i++) gd[i * 16 + hl] = zzb[(16 - i) & 15];
            if (hl == 0) g_C0t[b * 8 + segl] = Cb2;
        }
    }

    if (!full) return;     // block-uniform: tail blocks are done

    __syncthreads();

    // ---- phase 3: fold 8 -> 4 -> 2 -> 1, in place ----
    if (warp < 2) {
        int u = warp * 2 + half;
        matmul16(sA + (2 * u + 1) * MSLOT, sA + (2 * u) * MSLOT,
                 sA + (2 * u) * MSLOT, sC[2 * u + 1], sC[2 * u], &sC[2 * u], hl);
    }
    __syncthreads();
    if (warp == 0) {
        int u = half;
        matmul16(sA + (4 * u + 2) * MSLOT, sA + (4 * u) * MSLOT,
                 sA + (4 * u) * MSLOT, sC[4 * u + 2], sC[4 * u], &sC[4 * u], hl);
    }
    __syncthreads();
    if (warp == 0) {
        matmul16(sA + 4 * MSLOT, sA, sA, sC[4], sC[0], &sC[0], hl);
    }
    __syncthreads();

    if (tid < 256) {
        float* gp = g_P + ((size_t)b * 8 + c) * 256;
        gp[tid] = sA[(tid >> 4) * AROW + (tid & 15)];
        if (tid == 0) g_CP[b * 8 + c] = sC[0];
    }
}

// ---------------------------------------------------------------------------
// Kernel SCAN: 64 blocks x 256 threads.
//   stage <=15 matrices (chunks + tail level-0s) + tail w
//   CONCURRENTLY: warp 1 builds the rem-step tail matrix (e0-padded build)
//                 warp 0 runs the n_m matvecs + numerator reduce
//   then one barrier and warp 0 applies the tail matrix as a final matvec.
// ---------------------------------------------------------------------------
__global__ __launch_bounds__(256) void semicrf_scan(
    const int* __restrict__ lens,
    float*     __restrict__ out)
{
    __shared__ float sM[16 * MSLOT];     // slots 0..14 staged; slot 15 = tail matrix
    __shared__ int   sCm[16];
    __shared__ __align__(16) float sTW[256];   // raw tail w (16 steps x 16 taps)

    const int b    = blockIdx.x;
    const int tid  = threadIdx.x;
    const int warp = tid >> 5;
    const int lane = tid & 31;
    const int half = lane >> 4;
    const int hl   = lane & 15;

    const int len  = lens[b];
    const int m    = len >> 4;
    const int rem  = len & 15;
    const int qc   = m >> 3;
    const int tseg = m & 7;
    const int n_m  = qc + tseg;          // <= 15 staged matrices
    const int tot  = n_m * 256;

    // stage matrices: 15 independent predicated loads per thread, then store
    {
        float v[15];
#pragma unroll
        for (int r = 0; r < 15; r++) {
            int idx = tid + r * 256;
            float x = 0.0f;
            if (idx < tot) {
                int j = idx >> 8, pos = idx & 255;
                const float* src = (j < qc)
                    ? g_P   + ((size_t)b * 8 + j) * 256
                    : g_A0t + ((size_t)b * 8 + (j - qc)) * 256;
                x = src[pos];
            }
            v[r] = x;
        }
#pragma unroll
        for (int r = 0; r < 15; r++) {
            int idx = tid + r * 256;
            if (idx < tot) {
                int j = idx >> 8, pos = idx & 255;
                sM[j * MSLOT + (pos >> 4) * AROW + (pos & 15)] = v[r];
            }
        }
    }
    if (tid < n_m)
        sCm[tid] = (tid < qc) ? g_CP[b * 8 + tid] : g_C0t[b * 8 + (tid - qc)];

    if (rem > 0 && tid < 64) {
        reinterpret_cast<float4*>(sTW)[tid] =
            reinterpret_cast<const float4*>(g_tailw + b * 256)[tid];
    }
    __syncthreads();

    // numerator + matvec chain state live in warp 0 registers across phases
    float vf[16];
#pragma unroll
    for (int k = 0; k < 16; k++) vf[k] = (k == 0) ? 1.0f : 0.0f;
    int   Cv = 0;
    float ntv = 0.0f;

    // ---- warp 1: build the rem-step tail matrix into slot 15 (e0 trick) ----
    if (warp == 1 && rem > 0) {
        // overwrite steps [rem,16) with e0 -> pure shift steps
        for (int idx = lane; idx < (16 - rem) * 16; idx += 32) {
            int s = rem + (idx >> 4), j = idx & 15;
            sTW[s * 16 + j] = (j == 0) ? 1.0f : 0.0f;
        }
        __syncwarp();

        const float4* wv = reinterpret_cast<const float4*>(sTW);
        float zz[16];
#pragma unroll
        for (int k = 0; k < 16; k++) zz[k] = (k == ((16 - hl) & 15)) ? 1.0f : 0.0f;
        int C = 0;
#pragma unroll
        for (int s = 0; s < 16; s++) {
            float4 rr0 = wv[s * 4 + 0], rr1 = wv[s * 4 + 1];
            float4 rr2 = wv[s * 4 + 2], rr3 = wv[s * 4 + 3];

            float p3 = zz[(s - 15 + 32) & 15] * rr3.w;
            p3 = fmaf(zz[(s - 14 + 32) & 15], rr3.z, p3);
            p3 = fmaf(zz[(s - 13 + 32) & 15], rr3.y, p3);
            p3 = fmaf(zz[(s - 12 + 32) & 15], rr3.x, p3);
            float p2 = zz[(s - 11 + 32) & 15] * rr2.w;
            p2 = fmaf(zz[(s - 10 + 32) & 15], rr2.z, p2);
            p2 = fmaf(zz[(s -  9 + 32) & 15], rr2.y, p2);
            p2 = fmaf(zz[(s -  8 + 32) & 15], rr2.x, p2);
            float p1 = zz[(s -  7 + 32) & 15] * rr1.w;
            p1 = fmaf(zz[(s -  6 + 32) & 15], rr1.z, p1);
            p1 = fmaf(zz[(s -  5 + 32) & 15], rr1.y, p1);
            p1 = fmaf(zz[(s -  4 + 32) & 15], rr1.x, p1);
            float p0 = zz[(s -  3 + 32) & 15] * rr0.w;
            p0 = fmaf(zz[(s -  2 + 32) & 15], rr0.z, p0);
            p0 = fmaf(zz[(s -  1 + 32) & 15], rr0.y, p0);

            float zn = ((p3 + p2) + p1) + p0;
            zn = fmaf(zz[s & 15], rr0.x, zn);
            zz[(s + 1) & 15] = zn;

            if ((s & 3) == 3 && s != 15) {
                int ex = expo_(zn);
                ex = max(ex, __shfl_xor_sync(0xffffffffu, ex, 1, 16));
                ex = max(ex, __shfl_xor_sync(0xffffffffu, ex, 2, 16));
                ex = max(ex, __shfl_xor_sync(0xffffffffu, ex, 4, 16));
                ex = max(ex, __shfl_xor_sync(0xffffffffu, ex, 8, 16));
                int d = clampd_(ex - 127);
                C += d;
                float sc = __int_as_float((127 - d) << 23);
#pragma unroll
                for (int k2 = 0; k2 < 16; k2++) zz[k2] *= sc;
            }
        }
        {   // final renorm
            int ex = 0;
#pragma unroll
            for (int k = 0; k < 16; k++) ex = max(ex, expo_(zz[k]));
            ex = max(ex, __shfl_xor_sync(0xffffffffu, ex, 1, 16));
            ex = max(ex, __shfl_xor_sync(0xffffffffu, ex, 2, 16));
            ex = max(ex, __shfl_xor_sync(0xffffffffu, ex, 4, 16));
            ex = max(ex, __shfl_xor_sync(0xffffffffu, ex, 8, 16));
            int d = clampd_(ex - 127);
            C += d;
            float sc = __int_as_float((127 - d) << 23);
#pragma unroll
            for (int k = 0; k < 16; k++) zz[k] *= sc;
        }
        // store (half 0 only; no shuffles below, divergence safe)
        if (half == 0) {
            float* slot = sM + 15 * MSLOT;
#pragma unroll
            for (int i = 0; i < 16; i++) slot[i * AROW + hl] = zz[(16 - i) & 15];
            if (hl == 0) sCm[15] = C;
        }
    }

    // ---- warp 0: numerator reduce + main matvec chain (concurrent) ----
    if (warp == 0) {
        float nv = (lane < 8 && lane <= qc) ? g_nump[b * 8 + lane] : 0.0f;
#pragma unroll
        for (int o = 4; o > 0; o >>= 1) nv += __shfl_xor_sync(0xffffffffu, nv, o);
        ntv = __shfl_sync(0xffffffffu, nv, 0);

        for (int j = 0; j < n_m; j++)
            matvec16(sM + j * MSLOT, sCm[j], vf, Cv, hl);
    }

    __syncthreads();   // tail matrix ready; chain state in warp-0 registers

    if (warp == 0) {
        if (rem > 0)
            matvec16(sM + 15 * MSLOT, sCm[15], vf, Cv, hl);
        float den = ((float)Cv + lg2f_(vf[0])) * LN2;
        if (lane == 0) atomicAdd(out, den - ntv);
    }
}

// ---------------------------------------------------------------------------
extern "C" void kernel_launch(void* const* d_in, const int* in_sizes, int n_in,
                              void* d_out, int out_size)
{
    const float* tr   = (const float*)d_in[0];   // [B,S,L,T] f32
    const int*   tags = (const int*)  d_in[1];   // [B,S] i32
    const int*   lens = (const int*)  d_in[2];   // [B] i32
    float*       out  = (float*)d_out;           // scalar f32

    semicrf_fused<<<512, 512>>>(tr, tags, lens, out);   // R8/R11 fused (measured best)
    semicrf_scan<<<64, 256>>>(lens, out);               // overlapped tail-matrix scan
}